// round 9
// baseline (speedup 1.0000x reference)
#include <cuda_runtime.h>
#include <cuda_bf16.h>
#include <cstdint>

// ============================================================================
// PhaseMoE via mma.sync (HMMA m16n8k16 bf16) with hi/lo 3-MMA split.
// R8: 1024 threads (32 warps, 4x8 grid, 32x16 warp tile) -> occ 50%,
// forced 64-reg budget; corrected cp.async tail waits.
// tcgen05 unavailable (harness targets compute_103, not 103a).
// ============================================================================

#define B_TOK 32768
#define KEXP  8
#define EIN   1280
#define HID   128
#define LAT   256

#define ROWB   80            // padded bytes per 32-elem bf16 row
#define TILEB  (128 * ROWB)  // 10240 B per 128x32 tile

// smem map: 3 stage buffers x 4 tiles, then 4 h-chunks x hi/lo, then aux
#define STG(s, t) ((uint32_t)(((s) * 4 + (t)) * TILEB))   // t:0 Ahi 1 Alo 2 Bhi 3 Blo
#define HOF(c, h) ((uint32_t)((12 + (c) * 2 + (h)) * TILEB))
#define AUX       ((uint32_t)(20 * TILEB))                 // 204800
#define SMEM_TOTAL (20 * TILEB + 2048)                     // 206848

// ---- bf16 hi/lo scratch (__device__ globals: allocation-free) ----
__device__ __align__(16) __nv_bfloat16 g_xhi[(size_t)B_TOK * EIN];
__device__ __align__(16) __nv_bfloat16 g_xlo[(size_t)B_TOK * EIN];
__device__ __align__(16) __nv_bfloat16 g_w1hi[KEXP * HID * EIN];   // [e][n][k]
__device__ __align__(16) __nv_bfloat16 g_w1lo[KEXP * HID * EIN];
__device__ __align__(16) __nv_bfloat16 g_w2hi[KEXP * HID * HID];
__device__ __align__(16) __nv_bfloat16 g_w2lo[KEXP * HID * HID];
__device__ __align__(16) __nv_bfloat16 g_w3hi[KEXP * LAT * HID];
__device__ __align__(16) __nv_bfloat16 g_w3lo[KEXP * LAT * HID];

// ============================ helpers =======================================
__device__ __forceinline__ uint32_t smem_u32(const void* p) {
    uint32_t a;
    asm("{ .reg .u64 t; cvta.to.shared.u64 t, %1; cvt.u32.u64 %0, t; }"
        : "=r"(a) : "l"(p));
    return a;
}
__device__ __forceinline__ void cpasync16(uint32_t dst, const void* src) {
    asm volatile("cp.async.cg.shared.global [%0], [%1], 16;"
                 :: "r"(dst), "l"(src));
}
#define CP_COMMIT() asm volatile("cp.async.commit_group;" ::: "memory")
#define CP_WAIT1()  asm volatile("cp.async.wait_group 1;" ::: "memory")
#define CP_WAIT0()  asm volatile("cp.async.wait_group 0;" ::: "memory")

__device__ __forceinline__ void ldsm4(uint32_t addr, uint32_t* r) {
    asm volatile("ldmatrix.sync.aligned.m8n8.x4.shared.b16 {%0,%1,%2,%3}, [%4];"
                 : "=r"(r[0]), "=r"(r[1]), "=r"(r[2]), "=r"(r[3]) : "r"(addr));
}

__device__ __forceinline__ void mma16816(float* c, const uint32_t* a,
                                         uint32_t b0, uint32_t b1) {
    asm volatile(
        "mma.sync.aligned.m16n8k16.row.col.f32.bf16.bf16.f32 "
        "{%0,%1,%2,%3}, {%4,%5,%6,%7}, {%8,%9}, {%0,%1,%2,%3};"
        : "+f"(c[0]), "+f"(c[1]), "+f"(c[2]), "+f"(c[3])
        : "r"(a[0]), "r"(a[1]), "r"(a[2]), "r"(a[3]), "r"(b0), "r"(b1));
}

// stage one K=32 chunk: A hi/lo (x) + B hi/lo (weights). 1024 threads:
// each thread does one A-transfer and one B-transfer (16B cp.async).
__device__ __forceinline__ void stage4(uint32_t sb, int st,
        const __nv_bfloat16* xh, const __nv_bfloat16* xl,
        const __nv_bfloat16* wh, const __nv_bfloat16* wl,
        int lda, int ldb, int tid) {
    int half2nd = (tid >> 9) & 1;                 // 0: hi tiles, 1: lo tiles
    int j   = tid & 511;
    int row = j >> 2, c16 = j & 3;
    uint32_t off = (uint32_t)(row * ROWB + c16 * 16);
    const __nv_bfloat16* as = half2nd ? xl : xh;
    const __nv_bfloat16* bs = half2nd ? wl : wh;
    cpasync16(sb + STG(st, half2nd) + off,
              (const char*)as + (size_t)row * lda * 2 + c16 * 16);
    cpasync16(sb + STG(st, 2 + half2nd) + off,
              (const char*)bs + (size_t)row * ldb * 2 + c16 * 16);
}
// stage B hi/lo only (layers 2/3: A = h lives in smem already)
__device__ __forceinline__ void stage2(uint32_t sb, int st,
        const __nv_bfloat16* wh, const __nv_bfloat16* wl, int ldb, int tid) {
    int half2nd = (tid >> 9) & 1;
    int j   = tid & 511;
    int row = j >> 2, c16 = j & 3;
    const __nv_bfloat16* bs = half2nd ? wl : wh;
    cpasync16(sb + STG(st, 2 + half2nd) + (uint32_t)(row * ROWB + c16 * 16),
              (const char*)bs + (size_t)row * ldb * 2 + c16 * 16);
}

// one 32-wide K chunk of the 3-MMA split for a 32x16 warp tile
__device__ __forceinline__ void mma_chunk(float c[2][2][4], uint32_t sb,
        uint32_t Ahi, uint32_t Alo, uint32_t Bhi, uint32_t Blo,
        int wm, int wn, uint32_t aoff, uint32_t boff) {
#pragma unroll
    for (int ks = 0; ks < 2; ++ks) {
        uint32_t ah[2][4], al[2][4], bh[4], bl[4];
#pragma unroll
        for (int mt = 0; mt < 2; ++mt) {
            uint32_t base = (uint32_t)((wm * 32 + mt * 16) * ROWB + ks * 32) + aoff;
            ldsm4(sb + Ahi + base, ah[mt]);
            ldsm4(sb + Alo + base, al[mt]);
        }
        {
            uint32_t base = (uint32_t)((wn * 16) * ROWB + ks * 32) + boff;
            ldsm4(sb + Bhi + base, bh);
            ldsm4(sb + Blo + base, bl);
        }
#pragma unroll
        for (int mt = 0; mt < 2; ++mt)
#pragma unroll
            for (int nt = 0; nt < 2; ++nt) {
                mma16816(c[mt][nt], ah[mt], bh[nt * 2], bh[nt * 2 + 1]);
                mma16816(c[mt][nt], ah[mt], bl[nt * 2], bl[nt * 2 + 1]);
                mma16816(c[mt][nt], al[mt], bh[nt * 2], bh[nt * 2 + 1]);
            }
    }
}

__device__ __forceinline__ void split_pack(float h0, float h1,
                                           uint32_t& hip, uint32_t& lop) {
    __nv_bfloat16 h0h = __float2bfloat16(h0);
    __nv_bfloat16 h1h = __float2bfloat16(h1);
    hip = (uint32_t)__bfloat16_as_ushort(h0h) |
          ((uint32_t)__bfloat16_as_ushort(h1h) << 16);
    lop = (uint32_t)__bfloat16_as_ushort(__float2bfloat16(h0 - __bfloat162float(h0h))) |
          ((uint32_t)__bfloat16_as_ushort(__float2bfloat16(h1 - __bfloat162float(h1h))) << 16);
}

#define ZERO_C() do { \
    _Pragma("unroll") for (int mt = 0; mt < 2; ++mt) \
    _Pragma("unroll") for (int nt = 0; nt < 2; ++nt) \
    _Pragma("unroll") for (int q = 0; q < 4; ++q) c[mt][nt][q] = 0.f; } while (0)

// ======================= prep kernels =======================================
__global__ void convert_x_kernel(const float* __restrict__ u,
                                 const float* __restrict__ cond) {
    const int total = B_TOK * EIN;
    for (int i = blockIdx.x * blockDim.x + threadIdx.x; i < total;
         i += gridDim.x * blockDim.x) {
        int b = i / EIN, k = i - b * EIN;
        float v = (k < 256) ? u[(size_t)b * 256 + k]
                            : cond[(size_t)b * 1024 + (k - 256)];
        __nv_bfloat16 hi = __float2bfloat16(v);
        g_xhi[i] = hi;
        g_xlo[i] = __float2bfloat16(v - __bfloat162float(hi));
    }
}

__global__ void convert_w_kernel(const float* __restrict__ W1,
                                 const float* __restrict__ W2,
                                 const float* __restrict__ W3) {
    const int N1 = KEXP * HID * EIN;
    const int N2 = KEXP * HID * HID;
    const int N3 = KEXP * LAT * HID;
    const int total = N1 + N2 + N3;
    for (int i = blockIdx.x * blockDim.x + threadIdx.x; i < total;
         i += gridDim.x * blockDim.x) {
        float v;
        __nv_bfloat16 *dh, *dl;
        if (i < N1) {
            int e = i / (HID * EIN), r = i - e * (HID * EIN);
            int n = r / EIN, k = r - n * EIN;
            v = W1[((size_t)e * 1281 + k) * HID + n];
            dh = &g_w1hi[i]; dl = &g_w1lo[i];
        } else if (i < N1 + N2) {
            int j = i - N1;
            int e = j / (HID * HID), r = j - e * (HID * HID);
            int n = r / HID, k = r - n * HID;
            v = W2[((size_t)e * HID + k) * HID + n];
            dh = &g_w2hi[j]; dl = &g_w2lo[j];
        } else {
            int j = i - N1 - N2;
            int e = j / (LAT * HID), r = j - e * (LAT * HID);
            int n = r / HID, k = r - n * HID;
            v = W3[((size_t)e * HID + k) * LAT + n];
            dh = &g_w3hi[j]; dl = &g_w3lo[j];
        }
        __nv_bfloat16 hi = __float2bfloat16(v);
        *dh = hi;
        *dl = __float2bfloat16(v - __bfloat162float(hi));
    }
}

__global__ void init_out_kernel(const float* __restrict__ p_hat,
                                const float* __restrict__ b3,
                                float* __restrict__ out) {
    int i = blockIdx.x * blockDim.x + threadIdx.x;   // over B_TOK*LAT
    int b = i >> 8, c = i & 255;
    float s = 0.f;
#pragma unroll
    for (int k = 0; k < KEXP; ++k)
        s = fmaf(p_hat[(size_t)b * KEXP + k], b3[k * LAT + c], s);
    out[i] = s;
}

// =========================== main kernel ====================================
__global__ __launch_bounds__(1024, 1)
void phase_moe_mma(const float* __restrict__ tau,
                   const float* __restrict__ p_hat,
                   const float* __restrict__ W1,
                   const float* __restrict__ b1,
                   const float* __restrict__ b2,
                   float* __restrict__ out) {
    extern __shared__ __align__(128) char smem[];
    const uint32_t sb = smem_u32(smem);
    const int tid  = threadIdx.x;
    const int lane = tid & 31;
    const int w    = tid >> 5;          // 0..31
    const int wm   = w >> 3;            // 0..3  (32 rows each)
    const int wn   = w & 7;             // 0..7  (16 cols each)
    const int lr   = lane >> 2, lc = lane & 3;
    const int b0   = blockIdx.x * 128;

    // ldmatrix per-lane offsets
    const uint32_t aoff = (uint32_t)(((lane & 7) + ((lane >> 3) & 1) * 8) * ROWB
                                     + ((lane >> 4) & 1) * 16);
    const uint32_t boff = (uint32_t)(((lane & 7) + ((lane >> 4) & 1) * 8) * ROWB
                                     + ((lane >> 3) & 1) * 16);

    float* b1s  = reinterpret_cast<float*>(smem + AUX);          // 128
    float* b2s  = reinterpret_cast<float*>(smem + AUX + 512);    // 128
    float* w1l  = reinterpret_cast<float*>(smem + AUX + 1024);   // 128
    float* taus = reinterpret_cast<float*>(smem + AUX + 1536);   // 128

    if (tid < 128) taus[tid] = tau[b0 + tid];

    const __nv_bfloat16* xh = g_xhi + (size_t)b0 * EIN;
    const __nv_bfloat16* xl = g_xlo + (size_t)b0 * EIN;

    float c[2][2][4];

    for (int e = 0; e < KEXP; ++e) {
        __syncthreads();   // buffers + bias smem free for reuse
        if (tid < 128) {
            b1s[tid] = b1[e * HID + tid];
            b2s[tid] = b2[e * HID + tid];
            w1l[tid] = W1[((size_t)e * 1281 + 1280) * HID + tid];
        }

        // ---------------- layer 1: K=1280, 40 chunks ------------------------
        const __nv_bfloat16* w1h = g_w1hi + (size_t)e * HID * EIN;
        const __nv_bfloat16* w1o = g_w1lo + (size_t)e * HID * EIN;
        ZERO_C();
        stage4(sb, 0, xh,      xl,      w1h,      w1o,      EIN, EIN, tid); CP_COMMIT();
        stage4(sb, 1, xh + 32, xl + 32, w1h + 32, w1o + 32, EIN, EIN, tid); CP_COMMIT();
        for (int ch = 0; ch < 40; ++ch) {
            if (ch < 39) { CP_WAIT1(); } else { CP_WAIT0(); }
            __syncthreads();
            if (ch + 2 < 40) {
                int ko = (ch + 2) * 32;
                stage4(sb, (ch + 2) % 3, xh + ko, xl + ko, w1h + ko, w1o + ko,
                       EIN, EIN, tid);
                CP_COMMIT();
            }
            int st = ch % 3;
            mma_chunk(c, sb, STG(st, 0), STG(st, 1), STG(st, 2), STG(st, 3),
                      wm, wn, aoff, boff);
        }
        __syncthreads();   // all warps done reading stage buffers

        // prefetch L2 chunks 0,1 (overlaps epilogue)
        const __nv_bfloat16* w2h = g_w2hi + (size_t)e * HID * HID;
        const __nv_bfloat16* w2l = g_w2lo + (size_t)e * HID * HID;
        stage2(sb, 0, w2h,      w2l,      HID, tid); CP_COMMIT();
        stage2(sb, 1, w2h + 32, w2l + 32, HID, tid); CP_COMMIT();

        // L1 epilogue: +bias +tau*w1last, silu, split -> h tiles
#pragma unroll
        for (int mt = 0; mt < 2; ++mt)
#pragma unroll
            for (int nt = 0; nt < 2; ++nt)
#pragma unroll
                for (int pr = 0; pr < 2; ++pr) {
                    int m   = wm * 32 + mt * 16 + pr * 8 + lr;
                    int col = wn * 16 + nt * 8 + lc * 2;
                    float t  = taus[m];
                    float v0 = c[mt][nt][pr * 2]     + b1s[col]     + t * w1l[col];
                    float v1 = c[mt][nt][pr * 2 + 1] + b1s[col + 1] + t * w1l[col + 1];
                    float h0 = v0 / (1.f + __expf(-v0));
                    float h1 = v1 / (1.f + __expf(-v1));
                    uint32_t hip, lop;
                    split_pack(h0, h1, hip, lop);
                    uint32_t byte = (uint32_t)(m * ROWB + (col & 31) * 2);
                    int chk = col >> 5;
                    *(uint32_t*)(smem + HOF(chk, 0) + byte) = hip;
                    *(uint32_t*)(smem + HOF(chk, 1) + byte) = lop;
                }
        __syncthreads();   // h visible to all warps

        // ---------------- layer 2: K=128, 4 chunks --------------------------
        ZERO_C();
        for (int ch = 0; ch < 4; ++ch) {
            if (ch < 3) { CP_WAIT1(); } else { CP_WAIT0(); }
            __syncthreads();
            if (ch + 2 < 4) {
                int ko = (ch + 2) * 32;
                stage2(sb, (ch + 2) % 3, w2h + ko, w2l + ko, HID, tid);
                CP_COMMIT();
            }
            int st = ch % 3;
            mma_chunk(c, sb, HOF(ch, 0), HOF(ch, 1), STG(st, 2), STG(st, 3),
                      wm, wn, aoff, boff);
        }
        __syncthreads();

        // prefetch L3 nh=0 chunks 0,1
        const __nv_bfloat16* w3h = g_w3hi + (size_t)e * LAT * HID;
        const __nv_bfloat16* w3l = g_w3lo + (size_t)e * LAT * HID;
        stage2(sb, 0, w3h,      w3l,      HID, tid); CP_COMMIT();
        stage2(sb, 1, w3h + 32, w3l + 32, HID, tid); CP_COMMIT();

        // L2 epilogue: +bias, silu, *p -> h tiles
#pragma unroll
        for (int mt = 0; mt < 2; ++mt)
#pragma unroll
            for (int nt = 0; nt < 2; ++nt)
#pragma unroll
                for (int pr = 0; pr < 2; ++pr) {
                    int m   = wm * 32 + mt * 16 + pr * 8 + lr;
                    int col = wn * 16 + nt * 8 + lc * 2;
                    float pe = p_hat[(size_t)(b0 + m) * KEXP + e];
                    float v0 = c[mt][nt][pr * 2]     + b2s[col];
                    float v1 = c[mt][nt][pr * 2 + 1] + b2s[col + 1];
                    float h0 = pe * (v0 / (1.f + __expf(-v0)));
                    float h1 = pe * (v1 / (1.f + __expf(-v1)));
                    uint32_t hip, lop;
                    split_pack(h0, h1, hip, lop);
                    uint32_t byte = (uint32_t)(m * ROWB + (col & 31) * 2);
                    int chk = col >> 5;
                    *(uint32_t*)(smem + HOF(chk, 0) + byte) = hip;
                    *(uint32_t*)(smem + HOF(chk, 1) + byte) = lop;
                }
        __syncthreads();

        // ---------------- layer 3: two 128-col halves, K=128 ----------------
        for (int nh = 0; nh < 2; ++nh) {
            const __nv_bfloat16* bh = w3h + (size_t)nh * 128 * HID;
            const __nv_bfloat16* bl = w3l + (size_t)nh * 128 * HID;
            if (nh == 1) {
                __syncthreads();   // nh=0 readers done with stage buffers
                stage2(sb, 0, bh,      bl,      HID, tid); CP_COMMIT();
                stage2(sb, 1, bh + 32, bl + 32, HID, tid); CP_COMMIT();
            }
            ZERO_C();
            for (int ch = 0; ch < 4; ++ch) {
                if (ch < 3) { CP_WAIT1(); } else { CP_WAIT0(); }
                __syncthreads();
                if (ch + 2 < 4) {
                    int ko = (ch + 2) * 32;
                    stage2(sb, (ch + 2) % 3, bh + ko, bl + ko, HID, tid);
                    CP_COMMIT();
                }
                int st = ch % 3;
                mma_chunk(c, sb, HOF(ch, 0), HOF(ch, 1), STG(st, 2), STG(st, 3),
                          wm, wn, aoff, boff);
            }
            // epilogue: out += D3 (p folded into h2; base = sum_k p*b3 via init)
#pragma unroll
            for (int mt = 0; mt < 2; ++mt)
#pragma unroll
                for (int nt = 0; nt < 2; ++nt)
#pragma unroll
                    for (int pr = 0; pr < 2; ++pr) {
                        int m   = wm * 32 + mt * 16 + pr * 8 + lr;
                        int col = nh * 128 + wn * 16 + nt * 8 + lc * 2;
                        float* o = out + (size_t)(b0 + m) * LAT + col;
                        float2 v = *reinterpret_cast<float2*>(o);
                        v.x += c[mt][nt][pr * 2];
                        v.y += c[mt][nt][pr * 2 + 1];
                        *reinterpret_cast<float2*>(o) = v;
                    }
        }
    }  // experts
}

// ============================== launch ======================================
extern "C" void kernel_launch(void* const* d_in, const int* in_sizes, int n_in,
                              void* d_out, int out_size) {
    const float* cond = (const float*)d_in[0];
    const float* u    = (const float*)d_in[1];
    const float* tau  = (const float*)d_in[2];
    const float* p    = (const float*)d_in[3];
    const float* W1   = (const float*)d_in[4];
    const float* b1   = (const float*)d_in[5];
    const float* W2   = (const float*)d_in[6];
    const float* b2   = (const float*)d_in[7];
    const float* W3   = (const float*)d_in[8];
    const float* b3   = (const float*)d_in[9];
    float* out = (float*)d_out;

    static int configured = 0;
    if (!configured) {
        cudaFuncSetAttribute(phase_moe_mma,
                             cudaFuncAttributeMaxDynamicSharedMemorySize,
                             SMEM_TOTAL);
        configured = 1;
    }

    convert_x_kernel<<<8192, 256>>>(u, cond);
    convert_w_kernel<<<2048, 256>>>(W1, W2, W3);
    init_out_kernel<<<(B_TOK * LAT) / 256, 256>>>(p, b3, out);
    phase_moe_mma<<<B_TOK / 128, 1024, SMEM_TOTAL>>>(tau, p, W1, b1, b2, out);
}

// round 10
// speedup vs baseline: 1.1496x; 1.1496x over previous
#include <cuda_runtime.h>
#include <cuda_bf16.h>
#include <cstdint>

// ============================================================================
// PhaseMoE via mma.sync (HMMA m16n8k16 bf16), hi/lo 3-MMA split.
// R9: cp.async.bulk (single-instruction DMA per tile) replaces per-thread
// cp.async staging (which bound the kernel at LDGSTS rt=8cyc/op/SMSP).
// Global scratch holds PRE-PADDED chunk-contiguous tiles (128 rows x 80B).
// 512 threads, 4x4 warp grid, 32x32 warp tile (best R7 shape).
// ============================================================================

#define B_TOK 32768
#define KEXP  8
#define EIN   1280
#define HID   128
#define LAT   256

#define ROWB   80
#define TILEB  (128 * ROWB)     // 10240 B per 128x32 tile
#define TILEE  (128 * 40)       // 5120 bf16 elems per padded tile

// smem map: 3 stage buffers x 4 tiles, 4 h-chunks x hi/lo, aux
#define STG(s, t) ((uint32_t)(((s) * 4 + (t)) * TILEB))   // t:0 Ahi 1 Alo 2 Bhi 3 Blo
#define HOF(c, h) ((uint32_t)((12 + (c) * 2 + (h)) * TILEB))
#define AUX       ((uint32_t)(20 * TILEB))
#define SMEM_TOTAL (20 * TILEB + 4096)

// ---- pre-tiled bf16 hi/lo scratch (__device__ globals) ----
// x:  [256 tok-tiles][40 chunks][tile]   W1: [8 e][40 c][tile]
// W2: [8 e][4 c][tile]                   W3: [8 e][2 nh][4 c][tile]
__device__ __align__(16) __nv_bfloat16 g_xhi[(size_t)256 * 40 * TILEE];
__device__ __align__(16) __nv_bfloat16 g_xlo[(size_t)256 * 40 * TILEE];
__device__ __align__(16) __nv_bfloat16 g_w1hi[KEXP * 40 * TILEE];
__device__ __align__(16) __nv_bfloat16 g_w1lo[KEXP * 40 * TILEE];
__device__ __align__(16) __nv_bfloat16 g_w2hi[KEXP * 4 * TILEE];
__device__ __align__(16) __nv_bfloat16 g_w2lo[KEXP * 4 * TILEE];
__device__ __align__(16) __nv_bfloat16 g_w3hi[KEXP * 2 * 4 * TILEE];
__device__ __align__(16) __nv_bfloat16 g_w3lo[KEXP * 2 * 4 * TILEE];

// ============================ helpers =======================================
__device__ __forceinline__ uint32_t smem_u32(const void* p) {
    uint32_t a;
    asm("{ .reg .u64 t; cvta.to.shared.u64 t, %1; cvt.u32.u64 %0, t; }"
        : "=r"(a) : "l"(p));
    return a;
}
#define MBAR_INIT(mb, c) asm volatile("mbarrier.init.shared.b64 [%0], %1;" :: "r"(mb), "r"(c) : "memory")
#define MBAR_EXPECT_TX(mb, tx) asm volatile("mbarrier.arrive.expect_tx.shared.b64 _, [%0], %1;" :: "r"(mb), "r"(tx) : "memory")

__device__ __forceinline__ void bulk_g2s(uint32_t dst, const void* src,
                                         uint32_t bytes, uint32_t mb) {
    asm volatile(
        "cp.async.bulk.shared::cta.global.mbarrier::complete_tx::bytes "
        "[%0], [%1], %2, [%3];"
        :: "r"(dst), "l"(src), "r"(bytes), "r"(mb) : "memory");
}

__device__ __forceinline__ void mbar_wait(uint32_t mb, int parity) {
    asm volatile(
        "{\n\t.reg .pred P1;\n\t"
        "WAIT_%=:\n\t"
        "mbarrier.try_wait.parity.acquire.cta.shared::cta.b64 P1, [%0], %1, 0x989680;\n\t"
        "@P1 bra.uni DONE_%=;\n\t"
        "bra.uni WAIT_%=;\n\t"
        "DONE_%=:\n\t}"
        :: "r"(mb), "r"((uint32_t)parity) : "memory");
}

__device__ __forceinline__ void ldsm4(uint32_t addr, uint32_t* r) {
    asm volatile("ldmatrix.sync.aligned.m8n8.x4.shared.b16 {%0,%1,%2,%3}, [%4];"
                 : "=r"(r[0]), "=r"(r[1]), "=r"(r[2]), "=r"(r[3]) : "r"(addr));
}

__device__ __forceinline__ void mma16816(float* c, const uint32_t* a,
                                         uint32_t b0, uint32_t b1) {
    asm volatile(
        "mma.sync.aligned.m16n8k16.row.col.f32.bf16.bf16.f32 "
        "{%0,%1,%2,%3}, {%4,%5,%6,%7}, {%8,%9}, {%0,%1,%2,%3};"
        : "+f"(c[0]), "+f"(c[1]), "+f"(c[2]), "+f"(c[3])
        : "r"(a[0]), "r"(a[1]), "r"(a[2]), "r"(a[3]), "r"(b0), "r"(b1));
}

// one 32-wide K chunk of the 3-MMA split for a 32x32 warp tile
__device__ __forceinline__ void mma_chunk(float c[2][4][4], uint32_t sb,
        uint32_t Ahi, uint32_t Alo, uint32_t Bhi, uint32_t Blo,
        int wm, int wn, uint32_t aoff, uint32_t boff) {
#pragma unroll
    for (int ks = 0; ks < 2; ++ks) {
        uint32_t ah[2][4], al[2][4], bh[2][4], bl[2][4];
#pragma unroll
        for (int mt = 0; mt < 2; ++mt) {
            uint32_t base = (uint32_t)((wm * 32 + mt * 16) * ROWB + ks * 32) + aoff;
            ldsm4(sb + Ahi + base, ah[mt]);
            ldsm4(sb + Alo + base, al[mt]);
        }
#pragma unroll
        for (int pr = 0; pr < 2; ++pr) {
            uint32_t base = (uint32_t)((wn * 32 + pr * 16) * ROWB + ks * 32) + boff;
            ldsm4(sb + Bhi + base, bh[pr]);
            ldsm4(sb + Blo + base, bl[pr]);
        }
#pragma unroll
        for (int mt = 0; mt < 2; ++mt)
#pragma unroll
            for (int nt = 0; nt < 4; ++nt) {
                int pr = nt >> 1, hf = (nt & 1) * 2;
                mma16816(c[mt][nt], ah[mt], bh[pr][hf], bh[pr][hf + 1]);
                mma16816(c[mt][nt], ah[mt], bl[pr][hf], bl[pr][hf + 1]);
                mma16816(c[mt][nt], al[mt], bh[pr][hf], bh[pr][hf + 1]);
            }
    }
}

__device__ __forceinline__ void split_pack(float h0, float h1,
                                           uint32_t& hip, uint32_t& lop) {
    __nv_bfloat16 h0h = __float2bfloat16(h0);
    __nv_bfloat16 h1h = __float2bfloat16(h1);
    hip = (uint32_t)__bfloat16_as_ushort(h0h) |
          ((uint32_t)__bfloat16_as_ushort(h1h) << 16);
    lop = (uint32_t)__bfloat16_as_ushort(__float2bfloat16(h0 - __bfloat162float(h0h))) |
          ((uint32_t)__bfloat16_as_ushort(__float2bfloat16(h1 - __bfloat162float(h1h))) << 16);
}

#define ZERO_C() do { \
    _Pragma("unroll") for (int mt = 0; mt < 2; ++mt) \
    _Pragma("unroll") for (int nt = 0; nt < 4; ++nt) \
    _Pragma("unroll") for (int q = 0; q < 4; ++q) c[mt][nt][q] = 0.f; } while (0)

// ======================= prep kernels (tiled layout) ========================
__global__ void convert_x_kernel(const float* __restrict__ u,
                                 const float* __restrict__ cond) {
    const int total = B_TOK * EIN;
    for (int i = blockIdx.x * blockDim.x + threadIdx.x; i < total;
         i += gridDim.x * blockDim.x) {
        int b = i / EIN, k = i - b * EIN;
        float v = (k < 256) ? u[(size_t)b * 256 + k]
                            : cond[(size_t)b * 1024 + (k - 256)];
        int t = b >> 7, m = b & 127, c = k >> 5, kk = k & 31;
        size_t dst = ((size_t)(t * 40 + c) * 128 + m) * 40 + kk;
        __nv_bfloat16 hi = __float2bfloat16(v);
        g_xhi[dst] = hi;
        g_xlo[dst] = __float2bfloat16(v - __bfloat162float(hi));
    }
}

__global__ void convert_w_kernel(const float* __restrict__ W1,
                                 const float* __restrict__ W2,
                                 const float* __restrict__ W3) {
    const int N1 = KEXP * HID * EIN;
    const int N2 = KEXP * HID * HID;
    const int N3 = KEXP * LAT * HID;
    const int total = N1 + N2 + N3;
    for (int i = blockIdx.x * blockDim.x + threadIdx.x; i < total;
         i += gridDim.x * blockDim.x) {
        float v;
        size_t dst;
        __nv_bfloat16 *dh, *dl;
        if (i < N1) {
            int e = i / (HID * EIN), r = i - e * (HID * EIN);
            int n = r / EIN, k = r - n * EIN;
            int c = k >> 5, kk = k & 31;
            v = W1[((size_t)e * 1281 + k) * HID + n];
            dst = ((size_t)(e * 40 + c) * 128 + n) * 40 + kk;
            dh = g_w1hi; dl = g_w1lo;
        } else if (i < N1 + N2) {
            int j = i - N1;
            int e = j / (HID * HID), r = j - e * (HID * HID);
            int n = r / HID, k = r - n * HID;
            int c = k >> 5, kk = k & 31;
            v = W2[((size_t)e * HID + k) * HID + n];
            dst = ((size_t)(e * 4 + c) * 128 + n) * 40 + kk;
            dh = g_w2hi; dl = g_w2lo;
        } else {
            int j = i - N1 - N2;
            int e = j / (LAT * HID), r = j - e * (LAT * HID);
            int n = r / HID, k = r - n * HID;
            int nh = n >> 7, nn = n & 127, c = k >> 5, kk = k & 31;
            v = W3[((size_t)e * HID + k) * LAT + n];
            dst = ((size_t)((e * 2 + nh) * 4 + c) * 128 + nn) * 40 + kk;
            dh = g_w3hi; dl = g_w3lo;
        }
        __nv_bfloat16 hi = __float2bfloat16(v);
        dh[dst] = hi;
        dl[dst] = __float2bfloat16(v - __bfloat162float(hi));
    }
}

__global__ void init_out_kernel(const float* __restrict__ p_hat,
                                const float* __restrict__ b3,
                                float* __restrict__ out) {
    int i = blockIdx.x * blockDim.x + threadIdx.x;
    int b = i >> 8, c = i & 255;
    float s = 0.f;
#pragma unroll
    for (int k = 0; k < KEXP; ++k)
        s = fmaf(p_hat[(size_t)b * KEXP + k], b3[k * LAT + c], s);
    out[i] = s;
}

// =========================== main kernel ====================================
__global__ __launch_bounds__(512, 1)
void phase_moe_mma(const float* __restrict__ tau,
                   const float* __restrict__ p_hat,
                   const float* __restrict__ W1,
                   const float* __restrict__ b1,
                   const float* __restrict__ b2,
                   float* __restrict__ out) {
    extern __shared__ __align__(128) char smem[];
    const uint32_t sb = smem_u32(smem);
    const int tid  = threadIdx.x;
    const int lane = tid & 31;
    const int w    = tid >> 5;
    const int wm   = w >> 2, wn = w & 3;
    const int lr   = lane >> 2, lc = lane & 3;
    const int b0   = blockIdx.x * 128;
    const int btile = blockIdx.x;

    const uint32_t aoff = (uint32_t)(((lane & 7) + ((lane >> 3) & 1) * 8) * ROWB
                                     + ((lane >> 4) & 1) * 16);
    const uint32_t boff = (uint32_t)(((lane & 7) + ((lane >> 4) & 1) * 8) * ROWB
                                     + ((lane >> 3) & 1) * 16);

    float* b1s  = reinterpret_cast<float*>(smem + AUX);          // 128
    float* b2s  = reinterpret_cast<float*>(smem + AUX + 512);    // 128
    float* w1l  = reinterpret_cast<float*>(smem + AUX + 1024);   // 128
    float* taus = reinterpret_cast<float*>(smem + AUX + 1536);   // 128
    const uint32_t mb0 = sb + AUX + 2048;                        // 3 mbarriers

    if (tid == 0) {
        MBAR_INIT(mb0,      1);
        MBAR_INIT(mb0 + 8,  1);
        MBAR_INIT(mb0 + 16, 1);
    }
    if (tid < 128) taus[tid] = tau[b0 + tid];
    __syncthreads();   // mbarrier init visible before any expect_tx / wait

    int ph[3] = {0, 0, 0};
    float c[2][4][4];

    for (int e = 0; e < KEXP; ++e) {
        __syncthreads();   // all reads of stage/h/bias smem from prev expert done
        if (tid < 128) {
            b1s[tid] = b1[e * HID + tid];
            b2s[tid] = b2[e * HID + tid];
            w1l[tid] = W1[((size_t)e * 1281 + 1280) * HID + tid];
        }

        // ---------------- layer 1: K=1280, 40 chunks ------------------------
        const __nv_bfloat16* xh  = g_xhi  + (size_t)btile * 40 * TILEE;
        const __nv_bfloat16* xl  = g_xlo  + (size_t)btile * 40 * TILEE;
        const __nv_bfloat16* w1h = g_w1hi + (size_t)e * 40 * TILEE;
        const __nv_bfloat16* w1o = g_w1lo + (size_t)e * 40 * TILEE;
        ZERO_C();
        if (tid == 0) {
#pragma unroll
            for (int s = 0; s < 2; ++s) {
                uint32_t mb = mb0 + s * 8;
                MBAR_EXPECT_TX(mb, 4 * TILEB);
                bulk_g2s(sb + STG(s, 0), xh  + (size_t)s * TILEE, TILEB, mb);
                bulk_g2s(sb + STG(s, 1), xl  + (size_t)s * TILEE, TILEB, mb);
                bulk_g2s(sb + STG(s, 2), w1h + (size_t)s * TILEE, TILEB, mb);
                bulk_g2s(sb + STG(s, 3), w1o + (size_t)s * TILEE, TILEB, mb);
            }
        }
        for (int ch = 0; ch < 40; ++ch) {
            int st = ch % 3;
            mbar_wait(mb0 + st * 8, ph[st]); ph[st] ^= 1;
            __syncthreads();   // prev-chunk readers done -> safe to refill st+2
            if (tid == 0 && ch + 2 < 40) {
                int s2 = (ch + 2) % 3;
                uint32_t mb = mb0 + s2 * 8;
                size_t o = (size_t)(ch + 2) * TILEE;
                MBAR_EXPECT_TX(mb, 4 * TILEB);
                bulk_g2s(sb + STG(s2, 0), xh + o,  TILEB, mb);
                bulk_g2s(sb + STG(s2, 1), xl + o,  TILEB, mb);
                bulk_g2s(sb + STG(s2, 2), w1h + o, TILEB, mb);
                bulk_g2s(sb + STG(s2, 3), w1o + o, TILEB, mb);
            }
            mma_chunk(c, sb, STG(st, 0), STG(st, 1), STG(st, 2), STG(st, 3),
                      wm, wn, aoff, boff);
        }
        __syncthreads();   // all warps done reading stage buffers

        // prefetch L2 chunks 0,1 (overlaps epilogue)
        const __nv_bfloat16* w2h = g_w2hi + (size_t)e * 4 * TILEE;
        const __nv_bfloat16* w2l = g_w2lo + (size_t)e * 4 * TILEE;
        if (tid == 0) {
#pragma unroll
            for (int s = 0; s < 2; ++s) {
                uint32_t mb = mb0 + s * 8;
                MBAR_EXPECT_TX(mb, 2 * TILEB);
                bulk_g2s(sb + STG(s, 2), w2h + (size_t)s * TILEE, TILEB, mb);
                bulk_g2s(sb + STG(s, 3), w2l + (size_t)s * TILEE, TILEB, mb);
            }
        }

        // L1 epilogue: +bias +tau*w1last, silu, split -> h tiles (chunk = wn)
#pragma unroll
        for (int mt = 0; mt < 2; ++mt)
#pragma unroll
            for (int nt = 0; nt < 4; ++nt)
#pragma unroll
                for (int pr = 0; pr < 2; ++pr) {
                    int m   = wm * 32 + mt * 16 + pr * 8 + lr;
                    int col = wn * 32 + nt * 8 + lc * 2;
                    float t  = taus[m];
                    float v0 = c[mt][nt][pr * 2]     + b1s[col]     + t * w1l[col];
                    float v1 = c[mt][nt][pr * 2 + 1] + b1s[col + 1] + t * w1l[col + 1];
                    float h0 = v0 / (1.f + __expf(-v0));
                    float h1 = v1 / (1.f + __expf(-v1));
                    uint32_t hip, lop;
                    split_pack(h0, h1, hip, lop);
                    uint32_t byte = (uint32_t)(m * ROWB + (nt * 8 + lc * 2) * 2);
                    *(uint32_t*)(smem + HOF(wn, 0) + byte) = hip;
                    *(uint32_t*)(smem + HOF(wn, 1) + byte) = lop;
                }
        __syncthreads();   // h visible to all warps

        // ---------------- layer 2: K=128, 4 chunks --------------------------
        ZERO_C();
        for (int ch = 0; ch < 4; ++ch) {
            int st = ch % 3;
            mbar_wait(mb0 + st * 8, ph[st]); ph[st] ^= 1;
            __syncthreads();
            if (tid == 0 && ch + 2 < 4) {
                int s2 = (ch + 2) % 3;
                uint32_t mb = mb0 + s2 * 8;
                size_t o = (size_t)(ch + 2) * TILEE;
                MBAR_EXPECT_TX(mb, 2 * TILEB);
                bulk_g2s(sb + STG(s2, 2), w2h + o, TILEB, mb);
                bulk_g2s(sb + STG(s2, 3), w2l + o, TILEB, mb);
            }
            mma_chunk(c, sb, HOF(ch, 0), HOF(ch, 1), STG(st, 2), STG(st, 3),
                      wm, wn, aoff, boff);
        }
        __syncthreads();

        // prefetch L3 nh=0 chunks 0,1
        const __nv_bfloat16* w3h = g_w3hi + (size_t)e * 8 * TILEE;
        const __nv_bfloat16* w3l = g_w3lo + (size_t)e * 8 * TILEE;
        if (tid == 0) {
#pragma unroll
            for (int s = 0; s < 2; ++s) {
                uint32_t mb = mb0 + s * 8;
                MBAR_EXPECT_TX(mb, 2 * TILEB);
                bulk_g2s(sb + STG(s, 2), w3h + (size_t)s * TILEE, TILEB, mb);
                bulk_g2s(sb + STG(s, 3), w3l + (size_t)s * TILEE, TILEB, mb);
            }
        }

        // L2 epilogue: +bias, silu, *p -> h tiles
#pragma unroll
        for (int mt = 0; mt < 2; ++mt)
#pragma unroll
            for (int nt = 0; nt < 4; ++nt)
#pragma unroll
                for (int pr = 0; pr < 2; ++pr) {
                    int m   = wm * 32 + mt * 16 + pr * 8 + lr;
                    int col = wn * 32 + nt * 8 + lc * 2;
                    float pe = p_hat[(size_t)(b0 + m) * KEXP + e];
                    float v0 = c[mt][nt][pr * 2]     + b2s[col];
                    float v1 = c[mt][nt][pr * 2 + 1] + b2s[col + 1];
                    float h0 = pe * (v0 / (1.f + __expf(-v0)));
                    float h1 = pe * (v1 / (1.f + __expf(-v1)));
                    uint32_t hip, lop;
                    split_pack(h0, h1, hip, lop);
                    uint32_t byte = (uint32_t)(m * ROWB + (nt * 8 + lc * 2) * 2);
                    *(uint32_t*)(smem + HOF(wn, 0) + byte) = hip;
                    *(uint32_t*)(smem + HOF(wn, 1) + byte) = lop;
                }
        __syncthreads();

        // ---------------- layer 3: two 128-col halves, K=128 ----------------
        for (int nh = 0; nh < 2; ++nh) {
            const __nv_bfloat16* bh = w3h + (size_t)nh * 4 * TILEE;
            const __nv_bfloat16* bl = w3l + (size_t)nh * 4 * TILEE;
            if (nh == 1) {
                __syncthreads();   // nh=0 readers done with stage buffers
                if (tid == 0) {
#pragma unroll
                    for (int s = 0; s < 2; ++s) {
                        uint32_t mb = mb0 + s * 8;
                        MBAR_EXPECT_TX(mb, 2 * TILEB);
                        bulk_g2s(sb + STG(s, 2), bh + (size_t)s * TILEE, TILEB, mb);
                        bulk_g2s(sb + STG(s, 3), bl + (size_t)s * TILEE, TILEB, mb);
                    }
                }
            }
            ZERO_C();
            for (int ch = 0; ch < 4; ++ch) {
                int st = ch % 3;
                mbar_wait(mb0 + st * 8, ph[st]); ph[st] ^= 1;
                __syncthreads();
                if (tid == 0 && ch + 2 < 4) {
                    int s2 = (ch + 2) % 3;
                    uint32_t mb = mb0 + s2 * 8;
                    size_t o = (size_t)(ch + 2) * TILEE;
                    MBAR_EXPECT_TX(mb, 2 * TILEB);
                    bulk_g2s(sb + STG(s2, 2), bh + o, TILEB, mb);
                    bulk_g2s(sb + STG(s2, 3), bl + o, TILEB, mb);
                }
                mma_chunk(c, sb, HOF(ch, 0), HOF(ch, 1), STG(st, 2), STG(st, 3),
                          wm, wn, aoff, boff);
            }
            // epilogue: out += D3 (p folded into h2; base = sum_k p*b3 via init)
#pragma unroll
            for (int mt = 0; mt < 2; ++mt)
#pragma unroll
                for (int nt = 0; nt < 4; ++nt)
#pragma unroll
                    for (int pr = 0; pr < 2; ++pr) {
                        int m   = wm * 32 + mt * 16 + pr * 8 + lr;
                        int col = nh * 128 + wn * 32 + nt * 8 + lc * 2;
                        float* o = out + (size_t)(b0 + m) * LAT + col;
                        float2 v = *reinterpret_cast<float2*>(o);
                        v.x += c[mt][nt][pr * 2];
                        v.y += c[mt][nt][pr * 2 + 1];
                        *reinterpret_cast<float2*>(o) = v;
                    }
        }
    }  // experts
}

// ============================== launch ======================================
extern "C" void kernel_launch(void* const* d_in, const int* in_sizes, int n_in,
                              void* d_out, int out_size) {
    const float* cond = (const float*)d_in[0];
    const float* u    = (const float*)d_in[1];
    const float* tau  = (const float*)d_in[2];
    const float* p    = (const float*)d_in[3];
    const float* W1   = (const float*)d_in[4];
    const float* b1   = (const float*)d_in[5];
    const float* W2   = (const float*)d_in[6];
    const float* b2   = (const float*)d_in[7];
    const float* W3   = (const float*)d_in[8];
    const float* b3   = (const float*)d_in[9];
    float* out = (float*)d_out;

    static int configured = 0;
    if (!configured) {
        cudaFuncSetAttribute(phase_moe_mma,
                             cudaFuncAttributeMaxDynamicSharedMemorySize,
                             SMEM_TOTAL);
        configured = 1;
    }

    convert_x_kernel<<<8192, 256>>>(u, cond);
    convert_w_kernel<<<2048, 256>>>(W1, W2, W3);
    init_out_kernel<<<(B_TOK * LAT) / 256, 256>>>(p, b3, out);
    phase_moe_mma<<<B_TOK / 128, 512, SMEM_TOTAL>>>(tau, p, W1, b1, b2, out);
}

// round 12
// speedup vs baseline: 1.1569x; 1.0063x over previous
#include <cuda_runtime.h>
#include <cuda_bf16.h>
#include <cstdint>

// ============================================================================
// PhaseMoE via mma.sync (HMMA m16n8k16 bf16), hi/lo 3-MMA split.
// R11 = R10 (full/empty mbarrier producer-consumer ring, cp.async.bulk DMA)
// + the missing __syncthreads between the L2 consume loop and the L2 epilogue
// (fast warp overwrote HOF h-tiles while slow warps still read them -> the
// R10 rel_err 2e-3 race).
// 512 threads, 4x4 warp grid, 32x32 warp tile.
// ============================================================================

#define B_TOK 32768
#define KEXP  8
#define EIN   1280
#define HID   128
#define LAT   256

#define ROWB   80
#define TILEB  (128 * ROWB)     // 10240 B per 128x32 tile
#define TILEE  (128 * 40)       // 5120 bf16 elems per padded tile

// smem map: 3 stage buffers x 4 tiles, 4 h-chunks x hi/lo, aux
#define STG(s, t) ((uint32_t)(((s) * 4 + (t)) * TILEB))   // t:0 Ahi 1 Alo 2 Bhi 3 Blo
#define HOF(c, h) ((uint32_t)((12 + (c) * 2 + (h)) * TILEB))
#define AUX       ((uint32_t)(20 * TILEB))
#define SMEM_TOTAL (20 * TILEB + 4096)

// ---- pre-tiled bf16 hi/lo scratch (__device__ globals) ----
__device__ __align__(16) __nv_bfloat16 g_xhi[(size_t)256 * 40 * TILEE];
__device__ __align__(16) __nv_bfloat16 g_xlo[(size_t)256 * 40 * TILEE];
__device__ __align__(16) __nv_bfloat16 g_w1hi[KEXP * 40 * TILEE];
__device__ __align__(16) __nv_bfloat16 g_w1lo[KEXP * 40 * TILEE];
__device__ __align__(16) __nv_bfloat16 g_w2hi[KEXP * 4 * TILEE];
__device__ __align__(16) __nv_bfloat16 g_w2lo[KEXP * 4 * TILEE];
__device__ __align__(16) __nv_bfloat16 g_w3hi[KEXP * 2 * 4 * TILEE];
__device__ __align__(16) __nv_bfloat16 g_w3lo[KEXP * 2 * 4 * TILEE];

// ============================ helpers =======================================
__device__ __forceinline__ uint32_t smem_u32(const void* p) {
    uint32_t a;
    asm("{ .reg .u64 t; cvta.to.shared.u64 t, %1; cvt.u32.u64 %0, t; }"
        : "=r"(a) : "l"(p));
    return a;
}
#define MBAR_INIT(mb, c) asm volatile("mbarrier.init.shared.b64 [%0], %1;" :: "r"(mb), "r"(c) : "memory")
#define MBAR_EXPECT_TX(mb, tx) asm volatile("mbarrier.arrive.expect_tx.shared.b64 _, [%0], %1;" :: "r"(mb), "r"(tx) : "memory")
#define MBAR_ARRIVE(mb) asm volatile("mbarrier.arrive.shared.b64 _, [%0];" :: "r"(mb) : "memory")

__device__ __forceinline__ void bulk_g2s(uint32_t dst, const void* src,
                                         uint32_t bytes, uint32_t mb) {
    asm volatile(
        "cp.async.bulk.shared::cta.global.mbarrier::complete_tx::bytes "
        "[%0], [%1], %2, [%3];"
        :: "r"(dst), "l"(src), "r"(bytes), "r"(mb) : "memory");
}

__device__ __forceinline__ void mbar_wait(uint32_t mb, uint32_t parity) {
    asm volatile(
        "{\n\t.reg .pred P1;\n\t"
        "WAIT_%=:\n\t"
        "mbarrier.try_wait.parity.acquire.cta.shared::cta.b64 P1, [%0], %1, 0x989680;\n\t"
        "@P1 bra.uni DONE_%=;\n\t"
        "bra.uni WAIT_%=;\n\t"
        "DONE_%=:\n\t}"
        :: "r"(mb), "r"(parity) : "memory");
}

__device__ __forceinline__ void ldsm4(uint32_t addr, uint32_t* r) {
    asm volatile("ldmatrix.sync.aligned.m8n8.x4.shared.b16 {%0,%1,%2,%3}, [%4];"
                 : "=r"(r[0]), "=r"(r[1]), "=r"(r[2]), "=r"(r[3]) : "r"(addr));
}

__device__ __forceinline__ void mma16816(float* c, const uint32_t* a,
                                         uint32_t b0, uint32_t b1) {
    asm volatile(
        "mma.sync.aligned.m16n8k16.row.col.f32.bf16.bf16.f32 "
        "{%0,%1,%2,%3}, {%4,%5,%6,%7}, {%8,%9}, {%0,%1,%2,%3};"
        : "+f"(c[0]), "+f"(c[1]), "+f"(c[2]), "+f"(c[3])
        : "r"(a[0]), "r"(a[1]), "r"(a[2]), "r"(a[3]), "r"(b0), "r"(b1));
}

// one 32-wide K chunk of the 3-MMA split for a 32x32 warp tile
__device__ __forceinline__ void mma_chunk(float c[2][4][4], uint32_t sb,
        uint32_t Ahi, uint32_t Alo, uint32_t Bhi, uint32_t Blo,
        int wm, int wn, uint32_t aoff, uint32_t boff) {
#pragma unroll
    for (int ks = 0; ks < 2; ++ks) {
        uint32_t ah[2][4], al[2][4], bh[2][4], bl[2][4];
#pragma unroll
        for (int mt = 0; mt < 2; ++mt) {
            uint32_t base = (uint32_t)((wm * 32 + mt * 16) * ROWB + ks * 32) + aoff;
            ldsm4(sb + Ahi + base, ah[mt]);
            ldsm4(sb + Alo + base, al[mt]);
        }
#pragma unroll
        for (int pr = 0; pr < 2; ++pr) {
            uint32_t base = (uint32_t)((wn * 32 + pr * 16) * ROWB + ks * 32) + boff;
            ldsm4(sb + Bhi + base, bh[pr]);
            ldsm4(sb + Blo + base, bl[pr]);
        }
#pragma unroll
        for (int mt = 0; mt < 2; ++mt)
#pragma unroll
            for (int nt = 0; nt < 4; ++nt) {
                int pr = nt >> 1, hf = (nt & 1) * 2;
                mma16816(c[mt][nt], ah[mt], bh[pr][hf], bh[pr][hf + 1]);
                mma16816(c[mt][nt], ah[mt], bl[pr][hf], bl[pr][hf + 1]);
                mma16816(c[mt][nt], al[mt], bh[pr][hf], bh[pr][hf + 1]);
            }
    }
}

__device__ __forceinline__ void split_pack(float h0, float h1,
                                           uint32_t& hip, uint32_t& lop) {
    __nv_bfloat16 h0h = __float2bfloat16(h0);
    __nv_bfloat16 h1h = __float2bfloat16(h1);
    hip = (uint32_t)__bfloat16_as_ushort(h0h) |
          ((uint32_t)__bfloat16_as_ushort(h1h) << 16);
    lop = (uint32_t)__bfloat16_as_ushort(__float2bfloat16(h0 - __bfloat162float(h0h))) |
          ((uint32_t)__bfloat16_as_ushort(__float2bfloat16(h1 - __bfloat162float(h1h))) << 16);
}

#define ZERO_C() do { \
    _Pragma("unroll") for (int mt = 0; mt < 2; ++mt) \
    _Pragma("unroll") for (int nt = 0; nt < 4; ++nt) \
    _Pragma("unroll") for (int q = 0; q < 4; ++q) c[mt][nt][q] = 0.f; } while (0)

// ======================= prep kernels (tiled layout) ========================
__global__ void convert_x_kernel(const float* __restrict__ u,
                                 const float* __restrict__ cond) {
    const int total = B_TOK * EIN;
    for (int i = blockIdx.x * blockDim.x + threadIdx.x; i < total;
         i += gridDim.x * blockDim.x) {
        int b = i / EIN, k = i - b * EIN;
        float v = (k < 256) ? u[(size_t)b * 256 + k]
                            : cond[(size_t)b * 1024 + (k - 256)];
        int t = b >> 7, m = b & 127, c = k >> 5, kk = k & 31;
        size_t dst = ((size_t)(t * 40 + c) * 128 + m) * 40 + kk;
        __nv_bfloat16 hi = __float2bfloat16(v);
        g_xhi[dst] = hi;
        g_xlo[dst] = __float2bfloat16(v - __bfloat162float(hi));
    }
}

__global__ void convert_w_kernel(const float* __restrict__ W1,
                                 const float* __restrict__ W2,
                                 const float* __restrict__ W3) {
    const int N1 = KEXP * HID * EIN;
    const int N2 = KEXP * HID * HID;
    const int N3 = KEXP * LAT * HID;
    const int total = N1 + N2 + N3;
    for (int i = blockIdx.x * blockDim.x + threadIdx.x; i < total;
         i += gridDim.x * blockDim.x) {
        float v;
        size_t dst;
        __nv_bfloat16 *dh, *dl;
        if (i < N1) {
            int e = i / (HID * EIN), r = i - e * (HID * EIN);
            int n = r / EIN, k = r - n * EIN;
            int c = k >> 5, kk = k & 31;
            v = W1[((size_t)e * 1281 + k) * HID + n];
            dst = ((size_t)(e * 40 + c) * 128 + n) * 40 + kk;
            dh = g_w1hi; dl = g_w1lo;
        } else if (i < N1 + N2) {
            int j = i - N1;
            int e = j / (HID * HID), r = j - e * (HID * HID);
            int n = r / HID, k = r - n * HID;
            int c = k >> 5, kk = k & 31;
            v = W2[((size_t)e * HID + k) * HID + n];
            dst = ((size_t)(e * 4 + c) * 128 + n) * 40 + kk;
            dh = g_w2hi; dl = g_w2lo;
        } else {
            int j = i - N1 - N2;
            int e = j / (LAT * HID), r = j - e * (LAT * HID);
            int n = r / HID, k = r - n * HID;
            int nh = n >> 7, nn = n & 127, c = k >> 5, kk = k & 31;
            v = W3[((size_t)e * HID + k) * LAT + n];
            dst = ((size_t)((e * 2 + nh) * 4 + c) * 128 + nn) * 40 + kk;
            dh = g_w3hi; dl = g_w3lo;
        }
        __nv_bfloat16 hi = __float2bfloat16(v);
        dh[dst] = hi;
        dl[dst] = __float2bfloat16(v - __bfloat162float(hi));
    }
}

__global__ void init_out_kernel(const float* __restrict__ p_hat,
                                const float* __restrict__ b3,
                                float* __restrict__ out) {
    int i = blockIdx.x * blockDim.x + threadIdx.x;
    int b = i >> 8, c = i & 255;
    float s = 0.f;
#pragma unroll
    for (int k = 0; k < KEXP; ++k)
        s = fmaf(p_hat[(size_t)b * KEXP + k], b3[k * LAT + c], s);
    out[i] = s;
}

// =========================== main kernel ====================================
// full barrier at mb0 + s*16, empty barrier at mb0 + s*16 + 8.
// Producer (tid0): s = pg%3, wait empty parity ((pg/3)+1)&1, expect_tx, bulk.
// Consumer (all): s = cg%3, wait full parity (cg/3)&1, mma, warp-arrive empty.
#define FILL4(xh_, xl_, wh_, wl_) do { \
    int s_ = pg % 3; uint32_t par_ = (uint32_t)(((pg / 3) + 1) & 1); \
    uint32_t fb_ = mb0 + s_ * 16, eb_ = fb_ + 8; \
    mbar_wait(eb_, par_); \
    MBAR_EXPECT_TX(fb_, 4 * TILEB); \
    bulk_g2s(sb + STG(s_, 0), (xh_), TILEB, fb_); \
    bulk_g2s(sb + STG(s_, 1), (xl_), TILEB, fb_); \
    bulk_g2s(sb + STG(s_, 2), (wh_), TILEB, fb_); \
    bulk_g2s(sb + STG(s_, 3), (wl_), TILEB, fb_); \
    ++pg; } while (0)

#define FILL2(wh_, wl_) do { \
    int s_ = pg % 3; uint32_t par_ = (uint32_t)(((pg / 3) + 1) & 1); \
    uint32_t fb_ = mb0 + s_ * 16, eb_ = fb_ + 8; \
    mbar_wait(eb_, par_); \
    MBAR_EXPECT_TX(fb_, 2 * TILEB); \
    bulk_g2s(sb + STG(s_, 2), (wh_), TILEB, fb_); \
    bulk_g2s(sb + STG(s_, 3), (wl_), TILEB, fb_); \
    ++pg; } while (0)

__global__ __launch_bounds__(512, 1)
void phase_moe_mma(const float* __restrict__ tau,
                   const float* __restrict__ p_hat,
                   const float* __restrict__ W1,
                   const float* __restrict__ b1,
                   const float* __restrict__ b2,
                   float* __restrict__ out) {
    extern __shared__ __align__(128) char smem[];
    const uint32_t sb = smem_u32(smem);
    const int tid  = threadIdx.x;
    const int lane = tid & 31;
    const int w    = tid >> 5;
    const int wm   = w >> 2, wn = w & 3;
    const int lr   = lane >> 2, lc = lane & 3;
    const int b0   = blockIdx.x * 128;
    const int btile = blockIdx.x;

    const uint32_t aoff = (uint32_t)(((lane & 7) + ((lane >> 3) & 1) * 8) * ROWB
                                     + ((lane >> 4) & 1) * 16);
    const uint32_t boff = (uint32_t)(((lane & 7) + ((lane >> 4) & 1) * 8) * ROWB
                                     + ((lane >> 3) & 1) * 16);

    float* b1s  = reinterpret_cast<float*>(smem + AUX);          // 128
    float* b2s  = reinterpret_cast<float*>(smem + AUX + 512);    // 128
    float* w1l  = reinterpret_cast<float*>(smem + AUX + 1024);   // 128
    float* taus = reinterpret_cast<float*>(smem + AUX + 1536);   // 128
    const uint32_t mb0 = sb + AUX + 2048;                        // 3x(full,empty)

    if (tid == 0) {
#pragma unroll
        for (int s = 0; s < 3; ++s) {
            MBAR_INIT(mb0 + s * 16,     1);    // full: expect_tx arrival
            MBAR_INIT(mb0 + s * 16 + 8, 16);   // empty: one arrive per warp
        }
    }
    if (tid < 128) taus[tid] = tau[b0 + tid];
    __syncthreads();   // mbarrier init visible

    int pg = 0;   // producer fill counter (tid0)
    int cg = 0;   // consumer counter (all threads)
    float c[2][4][4];

    // consume current stage: wait full, mma, release empty
#define CONSUME(Ahi_, Alo_) do { \
    int s_ = cg % 3; uint32_t fb_ = mb0 + s_ * 16; \
    mbar_wait(fb_, (uint32_t)((cg / 3) & 1)); \
    mma_chunk(c, sb, (Ahi_), (Alo_), STG(s_, 2), STG(s_, 3), wm, wn, aoff, boff); \
    __syncwarp(); \
    if (lane == 0) MBAR_ARRIVE(fb_ + 8); \
    ++cg; } while (0)

    for (int e = 0; e < KEXP; ++e) {
        __syncthreads();   // bias smem reuse safe; h tiles free
        if (tid < 128) {
            b1s[tid] = b1[e * HID + tid];
            b2s[tid] = b2[e * HID + tid];
            w1l[tid] = W1[((size_t)e * 1281 + 1280) * HID + tid];
        }

        // ---------------- layer 1: K=1280, 40 chunks ------------------------
        const __nv_bfloat16* xh  = g_xhi  + (size_t)btile * 40 * TILEE;
        const __nv_bfloat16* xl  = g_xlo  + (size_t)btile * 40 * TILEE;
        const __nv_bfloat16* w1h = g_w1hi + (size_t)e * 40 * TILEE;
        const __nv_bfloat16* w1o = g_w1lo + (size_t)e * 40 * TILEE;
        ZERO_C();
        if (tid == 0) {
            FILL4(xh, xl, w1h, w1o);
            FILL4(xh + TILEE, xl + TILEE, w1h + TILEE, w1o + TILEE);
        }
        for (int ch = 0; ch < 40; ++ch) {
            if (tid == 0 && ch + 2 < 40) {
                size_t o = (size_t)(ch + 2) * TILEE;
                FILL4(xh + o, xl + o, w1h + o, w1o + o);
            }
            int s_ = cg % 3;
            CONSUME(STG(s_, 0), STG(s_, 1));
        }

        // producer: prefetch L2 chunks 0,1 (overlaps L1 epilogue for warps 1+)
        const __nv_bfloat16* w2h = g_w2hi + (size_t)e * 4 * TILEE;
        const __nv_bfloat16* w2l = g_w2lo + (size_t)e * 4 * TILEE;
        if (tid == 0) {
            FILL2(w2h, w2l);
            FILL2(w2h + TILEE, w2l + TILEE);
        }
        if (tid != 0) pg += 2;

        // L1 epilogue: +bias +tau*w1last, silu, split -> h tiles (chunk = wn)
        // (safe without a pre-barrier: L1 consume loop reads only STG tiles)
#pragma unroll
        for (int mt = 0; mt < 2; ++mt)
#pragma unroll
            for (int nt = 0; nt < 4; ++nt)
#pragma unroll
                for (int pr = 0; pr < 2; ++pr) {
                    int m   = wm * 32 + mt * 16 + pr * 8 + lr;
                    int col = wn * 32 + nt * 8 + lc * 2;
                    float t  = taus[m];
                    float v0 = c[mt][nt][pr * 2]     + b1s[col]     + t * w1l[col];
                    float v1 = c[mt][nt][pr * 2 + 1] + b1s[col + 1] + t * w1l[col + 1];
                    float h0 = v0 / (1.f + __expf(-v0));
                    float h1 = v1 / (1.f + __expf(-v1));
                    uint32_t hip, lop;
                    split_pack(h0, h1, hip, lop);
                    uint32_t byte = (uint32_t)(m * ROWB + (nt * 8 + lc * 2) * 2);
                    *(uint32_t*)(smem + HOF(wn, 0) + byte) = hip;
                    *(uint32_t*)(smem + HOF(wn, 1) + byte) = lop;
                }
        __syncthreads();   // h visible to all warps

        // ---------------- layer 2: K=128, 4 chunks --------------------------
        ZERO_C();
        for (int ch = 0; ch < 4; ++ch) {
            if (tid == 0 && ch + 2 < 4) {
                size_t o = (size_t)(ch + 2) * TILEE;
                FILL2(w2h + o, w2l + o);
            }
            if (tid != 0 && ch + 2 < 4) ++pg;
            CONSUME(HOF(ch, 0), HOF(ch, 1));
        }
        // RACE FIX (R10 bug): all warps must finish reading HOF h-tiles in the
        // L2 loop before any warp's L2 epilogue overwrites them.
        __syncthreads();

        // producer: prefetch L3 nh=0 chunks 0,1 (overlaps L2 epilogue)
        const __nv_bfloat16* w3h = g_w3hi + (size_t)e * 8 * TILEE;
        const __nv_bfloat16* w3l = g_w3lo + (size_t)e * 8 * TILEE;
        if (tid == 0) {
            FILL2(w3h, w3l);
            FILL2(w3h + TILEE, w3l + TILEE);
        }
        if (tid != 0) pg += 2;

        // L2 epilogue: +bias, silu, *p -> h tiles
#pragma unroll
        for (int mt = 0; mt < 2; ++mt)
#pragma unroll
            for (int nt = 0; nt < 4; ++nt)
#pragma unroll
                for (int pr = 0; pr < 2; ++pr) {
                    int m   = wm * 32 + mt * 16 + pr * 8 + lr;
                    int col = wn * 32 + nt * 8 + lc * 2;
                    float pe = p_hat[(size_t)(b0 + m) * KEXP + e];
                    float v0 = c[mt][nt][pr * 2]     + b2s[col];
                    float v1 = c[mt][nt][pr * 2 + 1] + b2s[col + 1];
                    float h0 = pe * (v0 / (1.f + __expf(-v0)));
                    float h1 = pe * (v1 / (1.f + __expf(-v1)));
                    uint32_t hip, lop;
                    split_pack(h0, h1, hip, lop);
                    uint32_t byte = (uint32_t)(m * ROWB + (nt * 8 + lc * 2) * 2);
                    *(uint32_t*)(smem + HOF(wn, 0) + byte) = hip;
                    *(uint32_t*)(smem + HOF(wn, 1) + byte) = lop;
                }
        __syncthreads();   // new h visible to all warps

        // ---------------- layer 3: two 128-col halves, K=128 ----------------
        // (HOF is read-only below; no further HOF writes this expert)
        for (int nh = 0; nh < 2; ++nh) {
            const __nv_bfloat16* bh = w3h + (size_t)nh * 4 * TILEE;
            const __nv_bfloat16* bl = w3l + (size_t)nh * 4 * TILEE;
            if (nh == 1) {
                if (tid == 0) {
                    FILL2(bh, bl);
                    FILL2(bh + TILEE, bl + TILEE);
                }
                if (tid != 0) pg += 2;
            }
            ZERO_C();
            for (int ch = 0; ch < 4; ++ch) {
                if (tid == 0 && ch + 2 < 4) {
                    size_t o = (size_t)(ch + 2) * TILEE;
                    FILL2(bh + o, bl + o);
                }
                if (tid != 0 && ch + 2 < 4) ++pg;
                CONSUME(HOF(ch, 0), HOF(ch, 1));
            }
            // epilogue: out += D3 (p folded into h2; base = sum_k p*b3 via init)
#pragma unroll
            for (int mt = 0; mt < 2; ++mt)
#pragma unroll
                for (int nt = 0; nt < 4; ++nt)
#pragma unroll
                    for (int pr = 0; pr < 2; ++pr) {
                        int m   = wm * 32 + mt * 16 + pr * 8 + lr;
                        int col = nh * 128 + wn * 32 + nt * 8 + lc * 2;
                        float* o = out + (size_t)(b0 + m) * LAT + col;
                        float2 v = *reinterpret_cast<float2*>(o);
                        v.x += c[mt][nt][pr * 2];
                        v.y += c[mt][nt][pr * 2 + 1];
                        *reinterpret_cast<float2*>(o) = v;
                    }
        }
    }  // experts
#undef CONSUME
}

// ============================== launch ======================================
extern "C" void kernel_launch(void* const* d_in, const int* in_sizes, int n_in,
                              void* d_out, int out_size) {
    const float* cond = (const float*)d_in[0];
    const float* u    = (const float*)d_in[1];
    const float* tau  = (const float*)d_in[2];
    const float* p    = (const float*)d_in[3];
    const float* W1   = (const float*)d_in[4];
    const float* b1   = (const float*)d_in[5];
    const float* W2   = (const float*)d_in[6];
    const float* b2   = (const float*)d_in[7];
    const float* W3   = (const float*)d_in[8];
    const float* b3   = (const float*)d_in[9];
    float* out = (float*)d_out;

    static int configured = 0;
    if (!configured) {
        cudaFuncSetAttribute(phase_moe_mma,
                             cudaFuncAttributeMaxDynamicSharedMemorySize,
                             SMEM_TOTAL);
        configured = 1;
    }

    convert_x_kernel<<<8192, 256>>>(u, cond);
    convert_w_kernel<<<2048, 256>>>(W1, W2, W3);
    init_out_kernel<<<(B_TOK * LAT) / 256, 256>>>(p, b3, out);
    phase_moe_mma<<<B_TOK / 128, 512, SMEM_TOTAL>>>(tau, p, W1, b1, b2, out);
}

// round 13
// speedup vs baseline: 1.2263x; 1.0600x over previous
#include <cuda_runtime.h>
#include <cuda_bf16.h>
#include <cstdint>

// ============================================================================
// PhaseMoE via mma.sync (HMMA m16n8k16 bf16), hi/lo 3-MMA split.
// R12 = R11 + de-phased consume: load ALL fragments (both ks) first, release
// the stage's empty barrier BEFORE the MMA burst (MMAs read registers), and
// hoist HOF A-fragment loads above the full-wait in L2/L3. This overlaps the
// per-chunk LDSM crossbar burst (~1000 cyc/SM) with the HMMA burst (~1536
// cyc) instead of serializing them via warp phase-lock.
// 512 threads, 4x4 warp grid, 32x32 warp tile.
// ============================================================================

#define B_TOK 32768
#define KEXP  8
#define EIN   1280
#define HID   128
#define LAT   256

#define ROWB   80
#define TILEB  (128 * ROWB)     // 10240 B per 128x32 tile
#define TILEE  (128 * 40)       // 5120 bf16 elems per padded tile

// smem map: 3 stage buffers x 4 tiles, 4 h-chunks x hi/lo, aux
#define STG(s, t) ((uint32_t)(((s) * 4 + (t)) * TILEB))   // t:0 Ahi 1 Alo 2 Bhi 3 Blo
#define HOF(c, h) ((uint32_t)((12 + (c) * 2 + (h)) * TILEB))
#define AUX       ((uint32_t)(20 * TILEB))
#define SMEM_TOTAL (20 * TILEB + 4096)

// ---- pre-tiled bf16 hi/lo scratch (__device__ globals) ----
__device__ __align__(16) __nv_bfloat16 g_xhi[(size_t)256 * 40 * TILEE];
__device__ __align__(16) __nv_bfloat16 g_xlo[(size_t)256 * 40 * TILEE];
__device__ __align__(16) __nv_bfloat16 g_w1hi[KEXP * 40 * TILEE];
__device__ __align__(16) __nv_bfloat16 g_w1lo[KEXP * 40 * TILEE];
__device__ __align__(16) __nv_bfloat16 g_w2hi[KEXP * 4 * TILEE];
__device__ __align__(16) __nv_bfloat16 g_w2lo[KEXP * 4 * TILEE];
__device__ __align__(16) __nv_bfloat16 g_w3hi[KEXP * 2 * 4 * TILEE];
__device__ __align__(16) __nv_bfloat16 g_w3lo[KEXP * 2 * 4 * TILEE];

// ============================ helpers =======================================
__device__ __forceinline__ uint32_t smem_u32(const void* p) {
    uint32_t a;
    asm("{ .reg .u64 t; cvta.to.shared.u64 t, %1; cvt.u32.u64 %0, t; }"
        : "=r"(a) : "l"(p));
    return a;
}
#define MBAR_INIT(mb, c) asm volatile("mbarrier.init.shared.b64 [%0], %1;" :: "r"(mb), "r"(c) : "memory")
#define MBAR_EXPECT_TX(mb, tx) asm volatile("mbarrier.arrive.expect_tx.shared.b64 _, [%0], %1;" :: "r"(mb), "r"(tx) : "memory")
#define MBAR_ARRIVE(mb) asm volatile("mbarrier.arrive.shared.b64 _, [%0];" :: "r"(mb) : "memory")

__device__ __forceinline__ void bulk_g2s(uint32_t dst, const void* src,
                                         uint32_t bytes, uint32_t mb) {
    asm volatile(
        "cp.async.bulk.shared::cta.global.mbarrier::complete_tx::bytes "
        "[%0], [%1], %2, [%3];"
        :: "r"(dst), "l"(src), "r"(bytes), "r"(mb) : "memory");
}

__device__ __forceinline__ void mbar_wait(uint32_t mb, uint32_t parity) {
    asm volatile(
        "{\n\t.reg .pred P1;\n\t"
        "WAIT_%=:\n\t"
        "mbarrier.try_wait.parity.acquire.cta.shared::cta.b64 P1, [%0], %1, 0x989680;\n\t"
        "@P1 bra.uni DONE_%=;\n\t"
        "bra.uni WAIT_%=;\n\t"
        "DONE_%=:\n\t}"
        :: "r"(mb), "r"(parity) : "memory");
}

__device__ __forceinline__ void ldsm4(uint32_t addr, uint32_t* r) {
    asm volatile("ldmatrix.sync.aligned.m8n8.x4.shared.b16 {%0,%1,%2,%3}, [%4];"
                 : "=r"(r[0]), "=r"(r[1]), "=r"(r[2]), "=r"(r[3]) : "r"(addr));
}

__device__ __forceinline__ void mma16816(float* c, const uint32_t* a,
                                         uint32_t b0, uint32_t b1) {
    asm volatile(
        "mma.sync.aligned.m16n8k16.row.col.f32.bf16.bf16.f32 "
        "{%0,%1,%2,%3}, {%4,%5,%6,%7}, {%8,%9}, {%0,%1,%2,%3};"
        : "+f"(c[0]), "+f"(c[1]), "+f"(c[2]), "+f"(c[3])
        : "r"(a[0]), "r"(a[1]), "r"(a[2]), "r"(a[3]), "r"(b0), "r"(b1));
}

// MMA burst over preloaded fragments (order identical to previous rounds)
__device__ __forceinline__ void mma_burst(float c[2][4][4],
        uint32_t ah[2][2][4], uint32_t al[2][2][4],
        uint32_t bh[2][2][4], uint32_t bl[2][2][4]) {
#pragma unroll
    for (int ks = 0; ks < 2; ++ks)
#pragma unroll
        for (int mt = 0; mt < 2; ++mt)
#pragma unroll
            for (int nt = 0; nt < 4; ++nt) {
                int pr = nt >> 1, hf = (nt & 1) * 2;
                mma16816(c[mt][nt], ah[ks][mt], bh[ks][pr][hf], bh[ks][pr][hf + 1]);
                mma16816(c[mt][nt], ah[ks][mt], bl[ks][pr][hf], bl[ks][pr][hf + 1]);
                mma16816(c[mt][nt], al[ks][mt], bh[ks][pr][hf], bh[ks][pr][hf + 1]);
            }
}

// L1 consume: A and B both live in the stage ring.
__device__ __forceinline__ void consume_l1(float c[2][4][4], uint32_t sb,
        int s, uint32_t fb, uint32_t parity,
        int wm, int wn, uint32_t aoff, uint32_t boff, int lane) {
    mbar_wait(fb, parity);
    uint32_t ah[2][2][4], al[2][2][4], bh[2][2][4], bl[2][2][4];
#pragma unroll
    for (int ks = 0; ks < 2; ++ks) {
#pragma unroll
        for (int mt = 0; mt < 2; ++mt) {
            uint32_t base = (uint32_t)((wm * 32 + mt * 16) * ROWB + ks * 32) + aoff;
            ldsm4(sb + STG(s, 0) + base, ah[ks][mt]);
            ldsm4(sb + STG(s, 1) + base, al[ks][mt]);
        }
#pragma unroll
        for (int pr = 0; pr < 2; ++pr) {
            uint32_t base = (uint32_t)((wn * 32 + pr * 16) * ROWB + ks * 32) + boff;
            ldsm4(sb + STG(s, 2) + base, bh[ks][pr]);
            ldsm4(sb + STG(s, 3) + base, bl[ks][pr]);
        }
    }
    __syncwarp();
    if (lane == 0) MBAR_ARRIVE(fb + 8);   // smem free; MMAs read registers
    mma_burst(c, ah, al, bh, bl);
}

// L2/L3 consume: A in HOF (stable), B in the stage ring.
// A-fragments load BEFORE the full-wait (hides wait latency).
__device__ __forceinline__ void consume_h(float c[2][4][4], uint32_t sb,
        uint32_t Ahi, uint32_t Alo, int s, uint32_t fb, uint32_t parity,
        int wm, int wn, uint32_t aoff, uint32_t boff, int lane) {
    uint32_t ah[2][2][4], al[2][2][4], bh[2][2][4], bl[2][2][4];
#pragma unroll
    for (int ks = 0; ks < 2; ++ks)
#pragma unroll
        for (int mt = 0; mt < 2; ++mt) {
            uint32_t base = (uint32_t)((wm * 32 + mt * 16) * ROWB + ks * 32) + aoff;
            ldsm4(sb + Ahi + base, ah[ks][mt]);
            ldsm4(sb + Alo + base, al[ks][mt]);
        }
    mbar_wait(fb, parity);
#pragma unroll
    for (int ks = 0; ks < 2; ++ks)
#pragma unroll
        for (int pr = 0; pr < 2; ++pr) {
            uint32_t base = (uint32_t)((wn * 32 + pr * 16) * ROWB + ks * 32) + boff;
            ldsm4(sb + STG(s, 2) + base, bh[ks][pr]);
            ldsm4(sb + STG(s, 3) + base, bl[ks][pr]);
        }
    __syncwarp();
    if (lane == 0) MBAR_ARRIVE(fb + 8);
    mma_burst(c, ah, al, bh, bl);
}

__device__ __forceinline__ void split_pack(float h0, float h1,
                                           uint32_t& hip, uint32_t& lop) {
    __nv_bfloat16 h0h = __float2bfloat16(h0);
    __nv_bfloat16 h1h = __float2bfloat16(h1);
    hip = (uint32_t)__bfloat16_as_ushort(h0h) |
          ((uint32_t)__bfloat16_as_ushort(h1h) << 16);
    lop = (uint32_t)__bfloat16_as_ushort(__float2bfloat16(h0 - __bfloat162float(h0h))) |
          ((uint32_t)__bfloat16_as_ushort(__float2bfloat16(h1 - __bfloat162float(h1h))) << 16);
}

#define ZERO_C() do { \
    _Pragma("unroll") for (int mt = 0; mt < 2; ++mt) \
    _Pragma("unroll") for (int nt = 0; nt < 4; ++nt) \
    _Pragma("unroll") for (int q = 0; q < 4; ++q) c[mt][nt][q] = 0.f; } while (0)

// ======================= prep kernels (tiled layout) ========================
__global__ void convert_x_kernel(const float* __restrict__ u,
                                 const float* __restrict__ cond) {
    const int total = B_TOK * EIN;
    for (int i = blockIdx.x * blockDim.x + threadIdx.x; i < total;
         i += gridDim.x * blockDim.x) {
        int b = i / EIN, k = i - b * EIN;
        float v = (k < 256) ? u[(size_t)b * 256 + k]
                            : cond[(size_t)b * 1024 + (k - 256)];
        int t = b >> 7, m = b & 127, c = k >> 5, kk = k & 31;
        size_t dst = ((size_t)(t * 40 + c) * 128 + m) * 40 + kk;
        __nv_bfloat16 hi = __float2bfloat16(v);
        g_xhi[dst] = hi;
        g_xlo[dst] = __float2bfloat16(v - __bfloat162float(hi));
    }
}

__global__ void convert_w_kernel(const float* __restrict__ W1,
                                 const float* __restrict__ W2,
                                 const float* __restrict__ W3) {
    const int N1 = KEXP * HID * EIN;
    const int N2 = KEXP * HID * HID;
    const int N3 = KEXP * LAT * HID;
    const int total = N1 + N2 + N3;
    for (int i = blockIdx.x * blockDim.x + threadIdx.x; i < total;
         i += gridDim.x * blockDim.x) {
        float v;
        size_t dst;
        __nv_bfloat16 *dh, *dl;
        if (i < N1) {
            int e = i / (HID * EIN), r = i - e * (HID * EIN);
            int n = r / EIN, k = r - n * EIN;
            int c = k >> 5, kk = k & 31;
            v = W1[((size_t)e * 1281 + k) * HID + n];
            dst = ((size_t)(e * 40 + c) * 128 + n) * 40 + kk;
            dh = g_w1hi; dl = g_w1lo;
        } else if (i < N1 + N2) {
            int j = i - N1;
            int e = j / (HID * HID), r = j - e * (HID * HID);
            int n = r / HID, k = r - n * HID;
            int c = k >> 5, kk = k & 31;
            v = W2[((size_t)e * HID + k) * HID + n];
            dst = ((size_t)(e * 4 + c) * 128 + n) * 40 + kk;
            dh = g_w2hi; dl = g_w2lo;
        } else {
            int j = i - N1 - N2;
            int e = j / (LAT * HID), r = j - e * (LAT * HID);
            int n = r / HID, k = r - n * HID;
            int nh = n >> 7, nn = n & 127, c = k >> 5, kk = k & 31;
            v = W3[((size_t)e * HID + k) * LAT + n];
            dst = ((size_t)((e * 2 + nh) * 4 + c) * 128 + nn) * 40 + kk;
            dh = g_w3hi; dl = g_w3lo;
        }
        __nv_bfloat16 hi = __float2bfloat16(v);
        dh[dst] = hi;
        dl[dst] = __float2bfloat16(v - __bfloat162float(hi));
    }
}

__global__ void init_out_kernel(const float* __restrict__ p_hat,
                                const float* __restrict__ b3,
                                float* __restrict__ out) {
    int i = blockIdx.x * blockDim.x + threadIdx.x;
    int b = i >> 8, c = i & 255;
    float s = 0.f;
#pragma unroll
    for (int k = 0; k < KEXP; ++k)
        s = fmaf(p_hat[(size_t)b * KEXP + k], b3[k * LAT + c], s);
    out[i] = s;
}

// =========================== main kernel ====================================
// full barrier at mb0 + s*16, empty barrier at mb0 + s*16 + 8.
#define FILL4(xh_, xl_, wh_, wl_) do { \
    int s_ = pg % 3; uint32_t par_ = (uint32_t)(((pg / 3) + 1) & 1); \
    uint32_t fb_ = mb0 + s_ * 16, eb_ = fb_ + 8; \
    mbar_wait(eb_, par_); \
    MBAR_EXPECT_TX(fb_, 4 * TILEB); \
    bulk_g2s(sb + STG(s_, 0), (xh_), TILEB, fb_); \
    bulk_g2s(sb + STG(s_, 1), (xl_), TILEB, fb_); \
    bulk_g2s(sb + STG(s_, 2), (wh_), TILEB, fb_); \
    bulk_g2s(sb + STG(s_, 3), (wl_), TILEB, fb_); \
    ++pg; } while (0)

#define FILL2(wh_, wl_) do { \
    int s_ = pg % 3; uint32_t par_ = (uint32_t)(((pg / 3) + 1) & 1); \
    uint32_t fb_ = mb0 + s_ * 16, eb_ = fb_ + 8; \
    mbar_wait(eb_, par_); \
    MBAR_EXPECT_TX(fb_, 2 * TILEB); \
    bulk_g2s(sb + STG(s_, 2), (wh_), TILEB, fb_); \
    bulk_g2s(sb + STG(s_, 3), (wl_), TILEB, fb_); \
    ++pg; } while (0)

__global__ __launch_bounds__(512, 1)
void phase_moe_mma(const float* __restrict__ tau,
                   const float* __restrict__ p_hat,
                   const float* __restrict__ W1,
                   const float* __restrict__ b1,
                   const float* __restrict__ b2,
                   float* __restrict__ out) {
    extern __shared__ __align__(128) char smem[];
    const uint32_t sb = smem_u32(smem);
    const int tid  = threadIdx.x;
    const int lane = tid & 31;
    const int w    = tid >> 5;
    const int wm   = w >> 2, wn = w & 3;
    const int lr   = lane >> 2, lc = lane & 3;
    const int b0   = blockIdx.x * 128;
    const int btile = blockIdx.x;

    const uint32_t aoff = (uint32_t)(((lane & 7) + ((lane >> 3) & 1) * 8) * ROWB
                                     + ((lane >> 4) & 1) * 16);
    const uint32_t boff = (uint32_t)(((lane & 7) + ((lane >> 4) & 1) * 8) * ROWB
                                     + ((lane >> 3) & 1) * 16);

    float* b1s  = reinterpret_cast<float*>(smem + AUX);          // 128
    float* b2s  = reinterpret_cast<float*>(smem + AUX + 512);    // 128
    float* w1l  = reinterpret_cast<float*>(smem + AUX + 1024);   // 128
    float* taus = reinterpret_cast<float*>(smem + AUX + 1536);   // 128
    const uint32_t mb0 = sb + AUX + 2048;                        // 3x(full,empty)

    if (tid == 0) {
#pragma unroll
        for (int s = 0; s < 3; ++s) {
            MBAR_INIT(mb0 + s * 16,     1);    // full: expect_tx arrival
            MBAR_INIT(mb0 + s * 16 + 8, 16);   // empty: one arrive per warp
        }
    }
    if (tid < 128) taus[tid] = tau[b0 + tid];
    __syncthreads();   // mbarrier init visible

    int pg = 0;   // producer fill counter (tid0)
    int cg = 0;   // consumer counter (all threads)
    float c[2][4][4];

    for (int e = 0; e < KEXP; ++e) {
        __syncthreads();   // bias smem reuse safe; h tiles free
        if (tid < 128) {
            b1s[tid] = b1[e * HID + tid];
            b2s[tid] = b2[e * HID + tid];
            w1l[tid] = W1[((size_t)e * 1281 + 1280) * HID + tid];
        }

        // ---------------- layer 1: K=1280, 40 chunks ------------------------
        const __nv_bfloat16* xh  = g_xhi  + (size_t)btile * 40 * TILEE;
        const __nv_bfloat16* xl  = g_xlo  + (size_t)btile * 40 * TILEE;
        const __nv_bfloat16* w1h = g_w1hi + (size_t)e * 40 * TILEE;
        const __nv_bfloat16* w1o = g_w1lo + (size_t)e * 40 * TILEE;
        ZERO_C();
        if (tid == 0) {
            FILL4(xh, xl, w1h, w1o);
            FILL4(xh + TILEE, xl + TILEE, w1h + TILEE, w1o + TILEE);
        }
        for (int ch = 0; ch < 40; ++ch) {
            if (tid == 0 && ch + 2 < 40) {
                size_t o = (size_t)(ch + 2) * TILEE;
                FILL4(xh + o, xl + o, w1h + o, w1o + o);
            }
            int s_ = cg % 3;
            consume_l1(c, sb, s_, mb0 + s_ * 16, (uint32_t)((cg / 3) & 1),
                       wm, wn, aoff, boff, lane);
            ++cg;
        }

        // producer: prefetch L2 chunks 0,1 (overlaps L1 epilogue)
        const __nv_bfloat16* w2h = g_w2hi + (size_t)e * 4 * TILEE;
        const __nv_bfloat16* w2l = g_w2lo + (size_t)e * 4 * TILEE;
        if (tid == 0) {
            FILL2(w2h, w2l);
            FILL2(w2h + TILEE, w2l + TILEE);
        }
        if (tid != 0) pg += 2;

        // L1 epilogue: +bias +tau*w1last, silu, split -> h tiles (chunk = wn)
#pragma unroll
        for (int mt = 0; mt < 2; ++mt)
#pragma unroll
            for (int nt = 0; nt < 4; ++nt)
#pragma unroll
                for (int pr = 0; pr < 2; ++pr) {
                    int m   = wm * 32 + mt * 16 + pr * 8 + lr;
                    int col = wn * 32 + nt * 8 + lc * 2;
                    float t  = taus[m];
                    float v0 = c[mt][nt][pr * 2]     + b1s[col]     + t * w1l[col];
                    float v1 = c[mt][nt][pr * 2 + 1] + b1s[col + 1] + t * w1l[col + 1];
                    float h0 = v0 / (1.f + __expf(-v0));
                    float h1 = v1 / (1.f + __expf(-v1));
                    uint32_t hip, lop;
                    split_pack(h0, h1, hip, lop);
                    uint32_t byte = (uint32_t)(m * ROWB + (nt * 8 + lc * 2) * 2);
                    *(uint32_t*)(smem + HOF(wn, 0) + byte) = hip;
                    *(uint32_t*)(smem + HOF(wn, 1) + byte) = lop;
                }
        __syncthreads();   // h visible to all warps

        // ---------------- layer 2: K=128, 4 chunks --------------------------
        ZERO_C();
        for (int ch = 0; ch < 4; ++ch) {
            if (tid == 0 && ch + 2 < 4) {
                size_t o = (size_t)(ch + 2) * TILEE;
                FILL2(w2h + o, w2l + o);
            }
            if (tid != 0 && ch + 2 < 4) ++pg;
            int s_ = cg % 3;
            consume_h(c, sb, HOF(ch, 0), HOF(ch, 1), s_, mb0 + s_ * 16,
                      (uint32_t)((cg / 3) & 1), wm, wn, aoff, boff, lane);
            ++cg;
        }
        // all warps must finish reading HOF before the L2 epilogue overwrites
        __syncthreads();

        // producer: prefetch L3 nh=0 chunks 0,1 (overlaps L2 epilogue)
        const __nv_bfloat16* w3h = g_w3hi + (size_t)e * 8 * TILEE;
        const __nv_bfloat16* w3l = g_w3lo + (size_t)e * 8 * TILEE;
        if (tid == 0) {
            FILL2(w3h, w3l);
            FILL2(w3h + TILEE, w3l + TILEE);
        }
        if (tid != 0) pg += 2;

        // L2 epilogue: +bias, silu, *p -> h tiles
#pragma unroll
        for (int mt = 0; mt < 2; ++mt)
#pragma unroll
            for (int nt = 0; nt < 4; ++nt)
#pragma unroll
                for (int pr = 0; pr < 2; ++pr) {
                    int m   = wm * 32 + mt * 16 + pr * 8 + lr;
                    int col = wn * 32 + nt * 8 + lc * 2;
                    float pe = p_hat[(size_t)(b0 + m) * KEXP + e];
                    float v0 = c[mt][nt][pr * 2]     + b2s[col];
                    float v1 = c[mt][nt][pr * 2 + 1] + b2s[col + 1];
                    float h0 = pe * (v0 / (1.f + __expf(-v0)));
                    float h1 = pe * (v1 / (1.f + __expf(-v1)));
                    uint32_t hip, lop;
                    split_pack(h0, h1, hip, lop);
                    uint32_t byte = (uint32_t)(m * ROWB + (nt * 8 + lc * 2) * 2);
                    *(uint32_t*)(smem + HOF(wn, 0) + byte) = hip;
                    *(uint32_t*)(smem + HOF(wn, 1) + byte) = lop;
                }
        __syncthreads();   // new h visible to all warps

        // ---------------- layer 3: two 128-col halves, K=128 ----------------
        for (int nh = 0; nh < 2; ++nh) {
            const __nv_bfloat16* bh = w3h + (size_t)nh * 4 * TILEE;
            const __nv_bfloat16* bl = w3l + (size_t)nh * 4 * TILEE;
            if (nh == 1) {
                if (tid == 0) {
                    FILL2(bh, bl);
                    FILL2(bh + TILEE, bl + TILEE);
                }
                if (tid != 0) pg += 2;
            }
            ZERO_C();
            for (int ch = 0; ch < 4; ++ch) {
                if (tid == 0 && ch + 2 < 4) {
                    size_t o = (size_t)(ch + 2) * TILEE;
                    FILL2(bh + o, bl + o);
                }
                if (tid != 0 && ch + 2 < 4) ++pg;
                int s_ = cg % 3;
                consume_h(c, sb, HOF(ch, 0), HOF(ch, 1), s_, mb0 + s_ * 16,
                          (uint32_t)((cg / 3) & 1), wm, wn, aoff, boff, lane);
                ++cg;
            }
            // epilogue: out += D3 (p folded into h2; base = sum_k p*b3 via init)
#pragma unroll
            for (int mt = 0; mt < 2; ++mt)
#pragma unroll
                for (int nt = 0; nt < 4; ++nt)
#pragma unroll
                    for (int pr = 0; pr < 2; ++pr) {
                        int m   = wm * 32 + mt * 16 + pr * 8 + lr;
                        int col = nh * 128 + wn * 32 + nt * 8 + lc * 2;
                        float* o = out + (size_t)(b0 + m) * LAT + col;
                        float2 v = *reinterpret_cast<float2*>(o);
                        v.x += c[mt][nt][pr * 2];
                        v.y += c[mt][nt][pr * 2 + 1];
                        *reinterpret_cast<float2*>(o) = v;
                    }
        }
    }  // experts
}

// ============================== launch ======================================
extern "C" void kernel_launch(void* const* d_in, const int* in_sizes, int n_in,
                              void* d_out, int out_size) {
    const float* cond = (const float*)d_in[0];
    const float* u    = (const float*)d_in[1];
    const float* tau  = (const float*)d_in[2];
    const float* p    = (const float*)d_in[3];
    const float* W1   = (const float*)d_in[4];
    const float* b1   = (const float*)d_in[5];
    const float* W2   = (const float*)d_in[6];
    const float* b2   = (const float*)d_in[7];
    const float* W3   = (const float*)d_in[8];
    const float* b3   = (const float*)d_in[9];
    float* out = (float*)d_out;

    static int configured = 0;
    if (!configured) {
        cudaFuncSetAttribute(phase_moe_mma,
                             cudaFuncAttributeMaxDynamicSharedMemorySize,
                             SMEM_TOTAL);
        configured = 1;
    }

    convert_x_kernel<<<8192, 256>>>(u, cond);
    convert_w_kernel<<<2048, 256>>>(W1, W2, W3);
    init_out_kernel<<<(B_TOK * LAT) / 256, 256>>>(p, b3, out);
    phase_moe_mma<<<B_TOK / 128, 512, SMEM_TOTAL>>>(tau, p, W1, b1, b2, out);
}